// round 1
// baseline (speedup 1.0000x reference)
#include <cuda_runtime.h>
#include <math.h>

// Shapes (fixed for this problem)
#define Bc   2
#define Lc   4096
#define Dc   1024
#define Hc   16
#define DHc  64
#define Mc   256
#define BHc  32
#define ROWS 8192   // B*L

// -------- scratch (device globals; no allocations allowed) --------
__device__ float g_q   [(size_t)ROWS * Dc];
__device__ float g_k   [(size_t)ROWS * Dc];
__device__ float g_v   [(size_t)ROWS * Dc];
__device__ float g_qf  [(size_t)BHc * Lc * Mc];
__device__ float g_kf  [(size_t)BHc * Lc * Mc];
__device__ float g_kv  [(size_t)BHc * Mc * DHc];
__device__ float g_ksum[(size_t)BHc * Mc];
__device__ float g_z   [(size_t)BHc * Lc];
__device__ float g_attn[(size_t)ROWS * Dc];
__device__ float g_y   [(size_t)ROWS * Dc];

// ============================================================
// SGEMM: C[M x 1024] = alpha * A[M x 1024] @ B[1024 x 1024], optional exact GELU
// 128x128 tile, BK=16, 256 threads, 8x8 per thread
// ============================================================
__global__ __launch_bounds__(256) void sgemm_kernel(
    const float* __restrict__ A, const float* __restrict__ B,
    float* __restrict__ C, float alpha, int do_gelu)
{
    const int K = 1024, N = 1024;
    __shared__ float As[16][128];
    __shared__ float Bs[16][128];

    const int bm = blockIdx.y * 128;
    const int bn = blockIdx.x * 128;
    const int tid = threadIdx.x;
    const int tr = (tid >> 4) << 3;   // 0..120
    const int tc = (tid & 15) << 3;   // 0..120

    float acc[8][8];
#pragma unroll
    for (int i = 0; i < 8; i++)
#pragma unroll
        for (int j = 0; j < 8; j++) acc[i][j] = 0.f;

    for (int kk = 0; kk < K; kk += 16) {
        // A tile: 128 rows x 16 cols = 512 float4
#pragma unroll
        for (int i = 0; i < 2; i++) {
            int s = tid + i * 256;           // 0..511
            int row = s >> 2;                // 0..127
            int c4 = (s & 3) << 2;           // 0,4,8,12
            float4 a = *(const float4*)&A[(size_t)(bm + row) * K + kk + c4];
            As[c4 + 0][row] = a.x; As[c4 + 1][row] = a.y;
            As[c4 + 2][row] = a.z; As[c4 + 3][row] = a.w;
        }
        // B tile: 16 rows x 128 cols = 512 float4
#pragma unroll
        for (int i = 0; i < 2; i++) {
            int s = tid + i * 256;
            int row = s >> 5;                // 0..15
            int c4 = (s & 31) << 2;          // 0..124
            *(float4*)&Bs[row][c4] = *(const float4*)&B[(size_t)(kk + row) * N + bn + c4];
        }
        __syncthreads();
#pragma unroll
        for (int k = 0; k < 16; k++) {
            float4 a0 = *(const float4*)&As[k][tr];
            float4 a1 = *(const float4*)&As[k][tr + 4];
            float4 b0 = *(const float4*)&Bs[k][tc];
            float4 b1 = *(const float4*)&Bs[k][tc + 4];
            float ra[8] = {a0.x, a0.y, a0.z, a0.w, a1.x, a1.y, a1.z, a1.w};
            float rb[8] = {b0.x, b0.y, b0.z, b0.w, b1.x, b1.y, b1.z, b1.w};
#pragma unroll
            for (int i = 0; i < 8; i++)
#pragma unroll
                for (int j = 0; j < 8; j++)
                    acc[i][j] += ra[i] * rb[j];
        }
        __syncthreads();
    }

#pragma unroll
    for (int i = 0; i < 8; i++) {
        float ov[8];
#pragma unroll
        for (int j = 0; j < 8; j++) {
            float t = acc[i][j] * alpha;
            if (do_gelu) t = 0.5f * t * (1.f + erff(t * 0.70710678118654752f));
            ov[j] = t;
        }
        float* cp = &C[(size_t)(bm + tr + i) * N + bn + tc];
        *(float4*)&cp[0] = make_float4(ov[0], ov[1], ov[2], ov[3]);
        *(float4*)&cp[4] = make_float4(ov[4], ov[5], ov[6], ov[7]);
    }
}

// ============================================================
// FAVOR+ feature kernel: for one (b,h) and a 32-row l-tile:
//   dash[l,m] = sum_d u[l,d]*proj[h,m,d];  F = exp(dash - 0.5*|u|^2 - rowmax)*M^-0.5
// smem: u[32][65] + proj[256][65] + dash[32][257]  (~105 KB dynamic)
// ============================================================
#define FEAT_SMEM_FLOATS (32*65 + 256*65 + 32*257)

__global__ __launch_bounds__(256) void feature_kernel(
    const float* __restrict__ S, const float* __restrict__ proj,
    float* __restrict__ F)
{
    extern __shared__ float sm[];
    float* us   = sm;                       // [32][65]
    float* ps   = sm + 32 * 65;             // [256][65]
    float* dash = sm + 32 * 65 + 256 * 65;  // [32][257]

    const int bh = blockIdx.y;
    const int b = bh >> 4, h = bh & 15;
    const int l0 = blockIdx.x * 32;
    const int tid = threadIdx.x;

    // load u tile 32x64
#pragma unroll
    for (int i = 0; i < 2; i++) {
        int s = tid + i * 256;               // 0..511 float4 slots
        int r = s >> 4;                      // 0..31
        int c4 = (s & 15) << 2;              // 0..60
        float4 a = *(const float4*)&S[(size_t)(b * Lc + l0 + r) * Dc + h * DHc + c4];
        us[r * 65 + c4 + 0] = a.x; us[r * 65 + c4 + 1] = a.y;
        us[r * 65 + c4 + 2] = a.z; us[r * 65 + c4 + 3] = a.w;
    }
    // load proj[h] 256x64
    const float* ph = proj + (size_t)h * Mc * DHc;
#pragma unroll
    for (int i = 0; i < 16; i++) {
        int s = tid + i * 256;               // 0..4095 float4 slots
        int r = s >> 4;                      // 0..255
        int c4 = (s & 15) << 2;
        float4 a = *(const float4*)&ph[r * 64 + c4];
        ps[r * 65 + c4 + 0] = a.x; ps[r * 65 + c4 + 1] = a.y;
        ps[r * 65 + c4 + 2] = a.z; ps[r * 65 + c4 + 3] = a.w;
    }
    __syncthreads();

    const int tr4 = (tid & 7) * 4;     // row group
    const int tm8 = (tid >> 3) * 8;    // m group
    float acc[4][8];
#pragma unroll
    for (int i = 0; i < 4; i++)
#pragma unroll
        for (int j = 0; j < 8; j++) acc[i][j] = 0.f;

#pragma unroll 8
    for (int d = 0; d < 64; d++) {
        float ur[4], pr[8];
#pragma unroll
        for (int i = 0; i < 4; i++) ur[i] = us[(tr4 + i) * 65 + d];
#pragma unroll
        for (int j = 0; j < 8; j++) pr[j] = ps[(tm8 + j) * 65 + d];
#pragma unroll
        for (int i = 0; i < 4; i++)
#pragma unroll
            for (int j = 0; j < 8; j++)
                acc[i][j] += ur[i] * pr[j];
    }
#pragma unroll
    for (int i = 0; i < 4; i++)
#pragma unroll
        for (int j = 0; j < 8; j++)
            dash[(tr4 + i) * 257 + tm8 + j] = acc[i][j];
    __syncthreads();

    const int w = tid >> 5, lane = tid & 31;
    for (int rr = w * 4; rr < w * 4 + 4; rr++) {
        float dv[8];
        float mx = -1e30f;
#pragma unroll
        for (int q = 0; q < 8; q++) {
            dv[q] = dash[rr * 257 + lane + q * 32];
            mx = fmaxf(mx, dv[q]);
        }
#pragma unroll
        for (int off = 16; off; off >>= 1)
            mx = fmaxf(mx, __shfl_xor_sync(0xffffffffu, mx, off));
        float u0 = us[rr * 65 + lane], u1 = us[rr * 65 + lane + 32];
        float dsq = u0 * u0 + u1 * u1;
#pragma unroll
        for (int off = 16; off; off >>= 1)
            dsq += __shfl_xor_sync(0xffffffffu, dsq, off);
        float base = -0.5f * dsq - mx;
        float* Fr = F + ((size_t)bh * Lc + l0 + rr) * Mc;
#pragma unroll
        for (int q = 0; q < 8; q++)
            Fr[lane + q * 32] = expf(dv[q] + base) * 0.0625f;   // * M^-0.5
    }
}

// ============================================================
// kv[m,d] = sum_l kf[l,m]*v[l,d];  ksum[m] = sum_l kf[l,m]
// grid: (bh=32, lsplit=16), atomicAdd partials (buffers pre-zeroed)
// ============================================================
__global__ __launch_bounds__(256) void kv_kernel(
    const float* __restrict__ kf, const float* __restrict__ v,
    float* __restrict__ kv, float* __restrict__ ksum)
{
    __shared__ float vs[16][64];
    const int bh = blockIdx.x;
    const int b = bh >> 4, h = bh & 15;
    const int l0 = blockIdx.y * 256;
    const int t = threadIdx.x;          // m index

    float acc[64];
#pragma unroll
    for (int d = 0; d < 64; d++) acc[d] = 0.f;
    float s = 0.f;

    for (int l = l0; l < l0 + 256; l += 16) {
        // stage 16 rows of v (head slice): 256 float4
        {
            int r = t >> 4, c4 = (t & 15) << 2;
            *(float4*)&vs[r][c4] =
                *(const float4*)&v[(size_t)(b * Lc + l + r) * Dc + h * DHc + c4];
        }
        __syncthreads();
#pragma unroll
        for (int r = 0; r < 16; r++) {
            float a = kf[((size_t)bh * Lc + l + r) * Mc + t];
            s += a;
#pragma unroll
            for (int d4 = 0; d4 < 16; d4++) {
                float4 vv = *(const float4*)&vs[r][d4 * 4];
                acc[d4 * 4 + 0] += a * vv.x;
                acc[d4 * 4 + 1] += a * vv.y;
                acc[d4 * 4 + 2] += a * vv.z;
                acc[d4 * 4 + 3] += a * vv.w;
            }
        }
        __syncthreads();
    }
    float* kvp = kv + ((size_t)bh * Mc + t) * DHc;
#pragma unroll
    for (int d = 0; d < 64; d++) atomicAdd(&kvp[d], acc[d]);
    atomicAdd(&ksum[bh * Mc + t], s);
}

// ============================================================
// z[bh,l] = 1 / (dot(qf[bh,l,:], ksum[bh,:]) + 1e-6)
// ============================================================
__global__ __launch_bounds__(256) void z_kernel(
    const float* __restrict__ qf, const float* __restrict__ ksum,
    float* __restrict__ z)
{
    __shared__ float ks[256];
    const int bh = blockIdx.y;
    ks[threadIdx.x] = ksum[bh * Mc + threadIdx.x];
    __syncthreads();
    const int w = threadIdx.x >> 5, lane = threadIdx.x & 31;
    const int l = blockIdx.x * 8 + w;
    const float* q = qf + ((size_t)bh * Lc + l) * Mc;
    float s = 0.f;
#pragma unroll
    for (int q8 = 0; q8 < 8; q8++) s += q[lane + q8 * 32] * ks[lane + q8 * 32];
#pragma unroll
    for (int off = 16; off; off >>= 1) s += __shfl_xor_sync(0xffffffffu, s, off);
    if (lane == 0) z[bh * Lc + l] = 1.0f / (s + 1e-6f);
}

// ============================================================
// attn[l, h*64+d] = z[l] * sum_m qf[l,m]*kv[m,d]
// per (bh): GEMM [128 x 64], K=256 (BK=32)
// ============================================================
__global__ __launch_bounds__(256) void attn_kernel(
    const float* __restrict__ qf, const float* __restrict__ kv,
    const float* __restrict__ z, float* __restrict__ attn)
{
    __shared__ float As[32][132];   // transposed qf chunk
    __shared__ float Bs[32][68];    // kv chunk
    const int bh = blockIdx.y;
    const int b = bh >> 4, h = bh & 15;
    const int l0 = blockIdx.x * 128;
    const int tid = threadIdx.x;
    const int tr = (tid >> 3) * 4;   // 0..124
    const int tc = (tid & 7) * 8;    // 0..56

    const float* qfb = qf + ((size_t)bh * Lc + l0) * Mc;
    const float* kvb = kv + (size_t)bh * Mc * DHc;

    float acc[4][8];
#pragma unroll
    for (int i = 0; i < 4; i++)
#pragma unroll
        for (int j = 0; j < 8; j++) acc[i][j] = 0.f;

    for (int kk = 0; kk < 256; kk += 32) {
        // qf tile: 128 x 32 = 1024 float4
#pragma unroll
        for (int i = 0; i < 4; i++) {
            int s = tid + i * 256;           // 0..1023
            int r = s >> 3;                  // 0..127
            int c4 = (s & 7) << 2;           // 0..28
            float4 a = *(const float4*)&qfb[(size_t)r * Mc + kk + c4];
            As[c4 + 0][r] = a.x; As[c4 + 1][r] = a.y;
            As[c4 + 2][r] = a.z; As[c4 + 3][r] = a.w;
        }
        // kv chunk: 32 x 64 = 512 float4
#pragma unroll
        for (int i = 0; i < 2; i++) {
            int s = tid + i * 256;
            int r = s >> 4;                  // 0..31
            int c4 = (s & 15) << 2;          // 0..60
            *(float4*)&Bs[r][c4] = *(const float4*)&kvb[(size_t)(kk + r) * 64 + c4];
        }
        __syncthreads();
#pragma unroll
        for (int k = 0; k < 32; k++) {
            float4 a0 = *(const float4*)&As[k][tr];
            float4 b0 = *(const float4*)&Bs[k][tc];
            float4 b1 = *(const float4*)&Bs[k][tc + 4];
            float ra[4] = {a0.x, a0.y, a0.z, a0.w};
            float rb[8] = {b0.x, b0.y, b0.z, b0.w, b1.x, b1.y, b1.z, b1.w};
#pragma unroll
            for (int i = 0; i < 4; i++)
#pragma unroll
                for (int j = 0; j < 8; j++)
                    acc[i][j] += ra[i] * rb[j];
        }
        __syncthreads();
    }
#pragma unroll
    for (int i = 0; i < 4; i++) {
        float zz = z[(size_t)bh * Lc + l0 + tr + i];
        float* ap = &attn[(size_t)(b * Lc + l0 + tr + i) * Dc + h * DHc + tc];
        *(float4*)&ap[0] = make_float4(acc[i][0]*zz, acc[i][1]*zz, acc[i][2]*zz, acc[i][3]*zz);
        *(float4*)&ap[4] = make_float4(acc[i][4]*zz, acc[i][5]*zz, acc[i][6]*zz, acc[i][7]*zz);
    }
}

// ============================================================
// LayerNorm over D=1024, then duplicate each row to out rows 2l and 2l+1
// ============================================================
__global__ __launch_bounds__(256) void ln_dup_kernel(
    const float* __restrict__ y, const float* __restrict__ g,
    const float* __restrict__ beta, float* __restrict__ out)
{
    __shared__ float red[18];
    const int row = blockIdx.x;             // 0..8191 (b*4096 + l)
    const int b = row >> 12, l = row & 4095;
    const int tid = threadIdx.x;
    const float* yr = y + (size_t)row * Dc;

    float v[4];
    float s = 0.f, ss = 0.f;
#pragma unroll
    for (int i = 0; i < 4; i++) {
        float t = yr[tid + i * 256];
        v[i] = t; s += t; ss += t * t;
    }
#pragma unroll
    for (int off = 16; off; off >>= 1) {
        s  += __shfl_xor_sync(0xffffffffu, s, off);
        ss += __shfl_xor_sync(0xffffffffu, ss, off);
    }
    const int w = tid >> 5, lane = tid & 31;
    if (lane == 0) { red[w] = s; red[8 + w] = ss; }
    __syncthreads();
    if (tid == 0) {
        float ts = 0.f, tss = 0.f;
#pragma unroll
        for (int i = 0; i < 8; i++) { ts += red[i]; tss += red[8 + i]; }
        float mean = ts * (1.0f / 1024.0f);
        float var = tss * (1.0f / 1024.0f) - mean * mean;
        red[16] = mean;
        red[17] = rsqrtf(var + 1e-5f);
    }
    __syncthreads();
    const float mean = red[16], rstd = red[17];
    float* o0 = out + ((size_t)b * 8192 + 2 * (size_t)l) * Dc;
#pragma unroll
    for (int i = 0; i < 4; i++) {
        int c = tid + i * 256;
        float o = (v[i] - mean) * rstd * g[c] + beta[c];
        o0[c] = o;
        o0[Dc + c] = o;
    }
}

// ============================================================
// host launch
// ============================================================
extern "C" void kernel_launch(void* const* d_in, const int* in_sizes, int n_in,
                              void* d_out, int out_size)
{
    const float* x    = (const float*)d_in[0];
    const float* Wq   = (const float*)d_in[1];
    const float* Wk   = (const float*)d_in[2];
    const float* Wv   = (const float*)d_in[3];
    const float* Wo   = (const float*)d_in[4];
    const float* proj = (const float*)d_in[5];
    const float* ln_g = (const float*)d_in[6];
    const float* ln_b = (const float*)d_in[7];
    float* out = (float*)d_out;

    float *q, *k, *v, *qf, *kf, *kv, *ksum, *z, *attn, *y;
    cudaGetSymbolAddress((void**)&q,    g_q);
    cudaGetSymbolAddress((void**)&k,    g_k);
    cudaGetSymbolAddress((void**)&v,    g_v);
    cudaGetSymbolAddress((void**)&qf,   g_qf);
    cudaGetSymbolAddress((void**)&kf,   g_kf);
    cudaGetSymbolAddress((void**)&kv,   g_kv);
    cudaGetSymbolAddress((void**)&ksum, g_ksum);
    cudaGetSymbolAddress((void**)&z,    g_z);
    cudaGetSymbolAddress((void**)&attn, g_attn);
    cudaGetSymbolAddress((void**)&y,    g_y);

    const float qscale = 0.35355339059327379f;  // DH^-0.25 = 64^-0.25

    dim3 gg(8, 64);  // N/128, M/128 for [8192 x 1024 x 1024]
    sgemm_kernel<<<gg, 256>>>(x, Wq, q, qscale, 0);
    sgemm_kernel<<<gg, 256>>>(x, Wk, k, qscale, 0);
    sgemm_kernel<<<gg, 256>>>(x, Wv, v, 1.0f, 0);

    const int feat_smem = FEAT_SMEM_FLOATS * (int)sizeof(float);
    cudaFuncSetAttribute(feature_kernel,
                         cudaFuncAttributeMaxDynamicSharedMemorySize, feat_smem);
    feature_kernel<<<dim3(Lc / 32, BHc), 256, feat_smem>>>(q, proj, qf);
    feature_kernel<<<dim3(Lc / 32, BHc), 256, feat_smem>>>(k, proj, kf);

    cudaMemsetAsync(kv,   0, (size_t)BHc * Mc * DHc * sizeof(float), 0);
    cudaMemsetAsync(ksum, 0, (size_t)BHc * Mc * sizeof(float), 0);
    kv_kernel<<<dim3(BHc, 16), 256>>>(kf, v, kv, ksum);

    z_kernel<<<dim3(Lc / 8, BHc), 256>>>(qf, ksum, z);
    attn_kernel<<<dim3(Lc / 128, BHc), 256>>>(qf, kv, z, attn);

    sgemm_kernel<<<gg, 256>>>(attn, Wo, y, 1.0f, 1);  // + exact GELU

    ln_dup_kernel<<<ROWS, 256>>>(y, ln_g, ln_b, out);
}

// round 3
// speedup vs baseline: 1.6127x; 1.6127x over previous
#include <cuda_runtime.h>
#include <cuda_bf16.h>
#include <math.h>
#include <stdint.h>

// Shapes (fixed)
#define Bc   2
#define Lc   4096
#define Dc   1024
#define Hc   16
#define DHc  64
#define Mc   256
#define BHc  32
#define ROWS 8192   // B*L

// -------- scratch (device globals; no allocations allowed) --------
__device__ float g_q   [(size_t)ROWS * Dc];
__device__ float g_k   [(size_t)ROWS * Dc];
__device__ float g_v   [(size_t)ROWS * Dc];
__device__ float g_qf  [(size_t)BHc * Lc * Mc];
__device__ float g_kf  [(size_t)BHc * Lc * Mc];
__device__ float g_kv  [(size_t)BHc * Mc * DHc];
__device__ float g_ksum[(size_t)BHc * Mc];
__device__ float g_z   [(size_t)BHc * Lc];
__device__ float g_attn[(size_t)ROWS * Dc];
__device__ float g_y   [(size_t)ROWS * Dc];
__device__ __nv_bfloat16 g_ahi[(size_t)ROWS * Dc];
__device__ __nv_bfloat16 g_alo[(size_t)ROWS * Dc];
__device__ __nv_bfloat16 g_bthi[(size_t)Dc * Dc];
__device__ __nv_bfloat16 g_btlo[(size_t)Dc * Dc];

// ================= baseline-PTX tensor-core helpers (sm_80+, no 'a' features) ==========
__device__ __forceinline__ uint32_t smem_u32(const void* p) {
    uint32_t a;
    asm("{ .reg .u64 t; cvta.to.shared.u64 t, %1; cvt.u32.u64 %0, t; }"
        : "=r"(a) : "l"(p));
    return a;
}
__device__ __forceinline__ void cp_async16(uint32_t saddr, const void* g) {
    asm volatile("cp.async.cg.shared.global [%0], [%1], 16;"
                 :: "r"(saddr), "l"(g) : "memory");
}
#define CP_COMMIT() asm volatile("cp.async.commit_group;" ::: "memory")
#define CP_WAIT(n)  asm volatile("cp.async.wait_group %0;" :: "n"(n) : "memory")

__device__ __forceinline__ void ldsm_x4(uint32_t r[4], uint32_t addr) {
    asm volatile("ldmatrix.sync.aligned.m8n8.x4.shared.b16 {%0,%1,%2,%3}, [%4];"
                 : "=r"(r[0]), "=r"(r[1]), "=r"(r[2]), "=r"(r[3]) : "r"(addr));
}
__device__ __forceinline__ void mma16816(float c[4], const uint32_t a[4],
                                         uint32_t b0, uint32_t b1) {
    asm volatile(
        "mma.sync.aligned.m16n8k16.row.col.f32.bf16.bf16.f32 "
        "{%0,%1,%2,%3}, {%4,%5,%6,%7}, {%8,%9}, {%0,%1,%2,%3};"
        : "+f"(c[0]), "+f"(c[1]), "+f"(c[2]), "+f"(c[3])
        : "r"(a[0]), "r"(a[1]), "r"(a[2]), "r"(a[3]), "r"(b0), "r"(b1));
}

// ============================================================
// fp32 -> (hi, lo) bf16 split
// ============================================================
__global__ __launch_bounds__(256) void split_kernel(
    const float* __restrict__ in, __nv_bfloat16* __restrict__ hi,
    __nv_bfloat16* __restrict__ lo, int n4)
{
    int i = blockIdx.x * 256 + threadIdx.x;
    if (i >= n4) return;
    float4 v = ((const float4*)in)[i];
    __nv_bfloat16 h0 = __float2bfloat16_rn(v.x);
    __nv_bfloat16 h1 = __float2bfloat16_rn(v.y);
    __nv_bfloat16 h2 = __float2bfloat16_rn(v.z);
    __nv_bfloat16 h3 = __float2bfloat16_rn(v.w);
    __nv_bfloat16 l0 = __float2bfloat16_rn(v.x - __bfloat162float(h0));
    __nv_bfloat16 l1 = __float2bfloat16_rn(v.y - __bfloat162float(h1));
    __nv_bfloat16 l2 = __float2bfloat16_rn(v.z - __bfloat162float(h2));
    __nv_bfloat16 l3 = __float2bfloat16_rn(v.w - __bfloat162float(h3));
    ((__nv_bfloat162*)hi)[2*i]   = __halves2bfloat162(h0, h1);
    ((__nv_bfloat162*)hi)[2*i+1] = __halves2bfloat162(h2, h3);
    ((__nv_bfloat162*)lo)[2*i]   = __halves2bfloat162(l0, l1);
    ((__nv_bfloat162*)lo)[2*i+1] = __halves2bfloat162(l2, l3);
}

// ============================================================
// W [K=1024, N=1024] -> W^T [N,K] with bf16 hi/lo split
// ============================================================
__global__ void tsplit_kernel(const float* __restrict__ W,
    __nv_bfloat16* __restrict__ Thi, __nv_bfloat16* __restrict__ Tlo)
{
    __shared__ float t[32][33];
    int bx = blockIdx.x * 32, by = blockIdx.y * 32;
    int tx = threadIdx.x, ty = threadIdx.y;   // 32 x 8
#pragma unroll
    for (int i = 0; i < 32; i += 8)
        t[ty + i][tx] = W[(size_t)(by + ty + i) * Dc + bx + tx];
    __syncthreads();
#pragma unroll
    for (int i = 0; i < 32; i += 8) {
        float v = t[tx][ty + i];
        int orow = bx + ty + i, ocol = by + tx;
        __nv_bfloat16 h = __float2bfloat16_rn(v);
        Thi[(size_t)orow * Dc + ocol] = h;
        Tlo[(size_t)orow * Dc + ocol] = __float2bfloat16_rn(v - __bfloat162float(h));
    }
}

// ============================================================
// bf16x3 tensor-core GEMM via mma.sync:
// C[8192 x 1024] = alpha * A @ Bt^T (+optional exact GELU)
// A hi/lo [ROWS x 1024] K-major; Bt hi/lo [1024 x 1024] (N,K) K-major.
// 3 accumulation passes: Ah*Bh, Ah*Bl, Al*Bh. CTA tile 128x128, BK=32,
// cp.async double buffer, 8 warps x (64x32 warp tile).
// ============================================================
#define LDT 40          // padded smem stride (bf16 elems): 80B, 16B-multiple
#define GNIT 96         // 3 passes * (1024/32)

__global__ __launch_bounds__(256) void mma_gemm_kernel(
    const __nv_bfloat16* __restrict__ Ahi, const __nv_bfloat16* __restrict__ Alo,
    const __nv_bfloat16* __restrict__ Bhi, const __nv_bfloat16* __restrict__ Blo,
    float* __restrict__ C, float alpha, int do_gelu)
{
    __shared__ __nv_bfloat16 As[2][128 * LDT];
    __shared__ __nv_bfloat16 Bs[2][128 * LDT];

    const int tid  = threadIdx.x;
    const int lane = tid & 31, wid = tid >> 5;
    const int bm = blockIdx.y * 128;
    const int bn = blockIdx.x * 128;
    const int wm = (wid >> 2) * 64;     // warp row offset in CTA tile
    const int wn = (wid & 3) * 32;      // warp col offset

    const uint32_t as_base[2] = {smem_u32(As[0]), smem_u32(As[1])};
    const uint32_t bs_base[2] = {smem_u32(Bs[0]), smem_u32(Bs[1])};

    // ldmatrix source addresses (element offsets precomputed per lane)
    const int a_row = wm + (lane & 15);           // + mi*16
    const int a_col = (lane >> 4) << 3;           // + k0
    const int b_row = wn + (lane & 7) + ((lane >> 4) << 3);  // + pair*16
    const int b_col = ((lane >> 3) & 1) << 3;     // + k0

    // global staging: each thread 2 x 16B per matrix per tile
    const int g_row0 = tid >> 2;                  // 0..63  (+64 for second)
    const int g_c8   = (tid & 3) << 3;            // 0,8,16,24

    auto stage = [&](int kt, int buf) {
        const int p  = kt >> 5;                   // pass 0,1,2
        const int kk = (kt & 31) << 5;            // k offset
        const __nv_bfloat16* Ag = (p < 2) ? Ahi : Alo;
        const __nv_bfloat16* Bg = (p == 1) ? Blo : Bhi;
#pragma unroll
        for (int i = 0; i < 2; i++) {
            int row = g_row0 + i * 64;
            uint32_t soff = (uint32_t)(row * LDT + g_c8) * 2;
            cp_async16(as_base[buf] + soff, Ag + (size_t)(bm + row) * Dc + kk + g_c8);
            cp_async16(bs_base[buf] + soff, Bg + (size_t)(bn + row) * Dc + kk + g_c8);
        }
        CP_COMMIT();
    };

    float acc[4][4][4];
#pragma unroll
    for (int mi = 0; mi < 4; mi++)
#pragma unroll
        for (int ni = 0; ni < 4; ni++)
#pragma unroll
            for (int e = 0; e < 4; e++) acc[mi][ni][e] = 0.f;

    stage(0, 0);
    stage(1, 1);

    for (int kt = 0; kt < GNIT; kt++) {
        const int buf = kt & 1;
        if (kt + 2 < GNIT) CP_WAIT(1); else CP_WAIT(0);
        __syncthreads();

#pragma unroll
        for (int k0 = 0; k0 < 32; k0 += 16) {
            uint32_t a[4][4];
#pragma unroll
            for (int mi = 0; mi < 4; mi++)
                ldsm_x4(a[mi], as_base[buf] +
                        (uint32_t)((a_row + mi * 16) * LDT + k0 + a_col) * 2);
            uint32_t b[2][4];
#pragma unroll
            for (int pr = 0; pr < 2; pr++)
                ldsm_x4(b[pr], bs_base[buf] +
                        (uint32_t)((b_row + pr * 16) * LDT + k0 + b_col) * 2);
#pragma unroll
            for (int mi = 0; mi < 4; mi++) {
                mma16816(acc[mi][0], a[mi], b[0][0], b[0][1]);
                mma16816(acc[mi][1], a[mi], b[0][2], b[0][3]);
                mma16816(acc[mi][2], a[mi], b[1][0], b[1][1]);
                mma16816(acc[mi][3], a[mi], b[1][2], b[1][3]);
            }
        }
        __syncthreads();
        if (kt + 2 < GNIT) stage(kt + 2, buf);
    }

    // epilogue: write 64x32 warp tile
    const int orow = bm + wm + (lane >> 2);
    const int ocol = bn + wn + ((lane & 3) << 1);
#pragma unroll
    for (int mi = 0; mi < 4; mi++) {
#pragma unroll
        for (int ni = 0; ni < 4; ni++) {
            float v0 = acc[mi][ni][0] * alpha;
            float v1 = acc[mi][ni][1] * alpha;
            float v2 = acc[mi][ni][2] * alpha;
            float v3 = acc[mi][ni][3] * alpha;
            if (do_gelu) {
                v0 = 0.5f * v0 * (1.f + erff(v0 * 0.70710678118654752f));
                v1 = 0.5f * v1 * (1.f + erff(v1 * 0.70710678118654752f));
                v2 = 0.5f * v2 * (1.f + erff(v2 * 0.70710678118654752f));
                v3 = 0.5f * v3 * (1.f + erff(v3 * 0.70710678118654752f));
            }
            float* p0 = &C[(size_t)(orow + mi * 16) * Dc + ocol + ni * 8];
            float* p1 = &C[(size_t)(orow + mi * 16 + 8) * Dc + ocol + ni * 8];
            *(float2*)p0 = make_float2(v0, v1);
            *(float2*)p1 = make_float2(v2, v3);
        }
    }
}

// ============================================================
// FAVOR+ feature kernel (unchanged, passing since R1)
// ============================================================
#define FEAT_SMEM_FLOATS (32*65 + 256*65 + 32*257)

__global__ __launch_bounds__(256) void feature_kernel(
    const float* __restrict__ S, const float* __restrict__ proj,
    float* __restrict__ F)
{
    extern __shared__ float sm[];
    float* us   = sm;
    float* ps   = sm + 32 * 65;
    float* dash = sm + 32 * 65 + 256 * 65;

    const int bh = blockIdx.y;
    const int b = bh >> 4, h = bh & 15;
    const int l0 = blockIdx.x * 32;
    const int tid = threadIdx.x;

#pragma unroll
    for (int i = 0; i < 2; i++) {
        int s = tid + i * 256;
        int r = s >> 4;
        int c4 = (s & 15) << 2;
        float4 a = *(const float4*)&S[(size_t)(b * Lc + l0 + r) * Dc + h * DHc + c4];
        us[r * 65 + c4 + 0] = a.x; us[r * 65 + c4 + 1] = a.y;
        us[r * 65 + c4 + 2] = a.z; us[r * 65 + c4 + 3] = a.w;
    }
    const float* ph = proj + (size_t)h * Mc * DHc;
#pragma unroll
    for (int i = 0; i < 16; i++) {
        int s = tid + i * 256;
        int r = s >> 4;
        int c4 = (s & 15) << 2;
        float4 a = *(const float4*)&ph[r * 64 + c4];
        ps[r * 65 + c4 + 0] = a.x; ps[r * 65 + c4 + 1] = a.y;
        ps[r * 65 + c4 + 2] = a.z; ps[r * 65 + c4 + 3] = a.w;
    }
    __syncthreads();

    const int tr4 = (tid & 7) * 4;
    const int tm8 = (tid >> 3) * 8;
    float acc[4][8];
#pragma unroll
    for (int i = 0; i < 4; i++)
#pragma unroll
        for (int j = 0; j < 8; j++) acc[i][j] = 0.f;

#pragma unroll 8
    for (int d = 0; d < 64; d++) {
        float ur[4], pr[8];
#pragma unroll
        for (int i = 0; i < 4; i++) ur[i] = us[(tr4 + i) * 65 + d];
#pragma unroll
        for (int j = 0; j < 8; j++) pr[j] = ps[(tm8 + j) * 65 + d];
#pragma unroll
        for (int i = 0; i < 4; i++)
#pragma unroll
            for (int j = 0; j < 8; j++)
                acc[i][j] += ur[i] * pr[j];
    }
#pragma unroll
    for (int i = 0; i < 4; i++)
#pragma unroll
        for (int j = 0; j < 8; j++)
            dash[(tr4 + i) * 257 + tm8 + j] = acc[i][j];
    __syncthreads();

    const int w = tid >> 5, lane = tid & 31;
    for (int rr = w * 4; rr < w * 4 + 4; rr++) {
        float dv[8];
        float mx = -1e30f;
#pragma unroll
        for (int q = 0; q < 8; q++) {
            dv[q] = dash[rr * 257 + lane + q * 32];
            mx = fmaxf(mx, dv[q]);
        }
#pragma unroll
        for (int off = 16; off; off >>= 1)
            mx = fmaxf(mx, __shfl_xor_sync(0xffffffffu, mx, off));
        float u0 = us[rr * 65 + lane], u1 = us[rr * 65 + lane + 32];
        float dsq = u0 * u0 + u1 * u1;
#pragma unroll
        for (int off = 16; off; off >>= 1)
            dsq += __shfl_xor_sync(0xffffffffu, dsq, off);
        float base = -0.5f * dsq - mx;
        float* Fr = F + ((size_t)bh * Lc + l0 + rr) * Mc;
#pragma unroll
        for (int q = 0; q < 8; q++)
            Fr[lane + q * 32] = expf(dv[q] + base) * 0.0625f;
    }
}

// ============================================================
// kv / z / attn / ln_dup (unchanged, passing since R1)
// ============================================================
__global__ __launch_bounds__(256) void kv_kernel(
    const float* __restrict__ kf, const float* __restrict__ v,
    float* __restrict__ kv, float* __restrict__ ksum)
{
    __shared__ float vs[16][64];
    const int bh = blockIdx.x;
    const int b = bh >> 4, h = bh & 15;
    const int l0 = blockIdx.y * 256;
    const int t = threadIdx.x;

    float acc[64];
#pragma unroll
    for (int d = 0; d < 64; d++) acc[d] = 0.f;
    float s = 0.f;

    for (int l = l0; l < l0 + 256; l += 16) {
        {
            int r = t >> 4, c4 = (t & 15) << 2;
            *(float4*)&vs[r][c4] =
                *(const float4*)&v[(size_t)(b * Lc + l + r) * Dc + h * DHc + c4];
        }
        __syncthreads();
#pragma unroll
        for (int r = 0; r < 16; r++) {
            float a = kf[((size_t)bh * Lc + l + r) * Mc + t];
            s += a;
#pragma unroll
            for (int d4 = 0; d4 < 16; d4++) {
                float4 vv = *(const float4*)&vs[r][d4 * 4];
                acc[d4 * 4 + 0] += a * vv.x;
                acc[d4 * 4 + 1] += a * vv.y;
                acc[d4 * 4 + 2] += a * vv.z;
                acc[d4 * 4 + 3] += a * vv.w;
            }
        }
        __syncthreads();
    }
    float* kvp = kv + ((size_t)bh * Mc + t) * DHc;
#pragma unroll
    for (int d = 0; d < 64; d++) atomicAdd(&kvp[d], acc[d]);
    atomicAdd(&ksum[bh * Mc + t], s);
}

__global__ __launch_bounds__(256) void z_kernel(
    const float* __restrict__ qf, const float* __restrict__ ksum,
    float* __restrict__ z)
{
    __shared__ float ks[256];
    const int bh = blockIdx.y;
    ks[threadIdx.x] = ksum[bh * Mc + threadIdx.x];
    __syncthreads();
    const int w = threadIdx.x >> 5, lane = threadIdx.x & 31;
    const int l = blockIdx.x * 8 + w;
    const float* q = qf + ((size_t)bh * Lc + l) * Mc;
    float s = 0.f;
#pragma unroll
    for (int q8 = 0; q8 < 8; q8++) s += q[lane + q8 * 32] * ks[lane + q8 * 32];
#pragma unroll
    for (int off = 16; off; off >>= 1) s += __shfl_xor_sync(0xffffffffu, s, off);
    if (lane == 0) z[bh * Lc + l] = 1.0f / (s + 1e-6f);
}

__global__ __launch_bounds__(256) void attn_kernel(
    const float* __restrict__ qf, const float* __restrict__ kv,
    const float* __restrict__ z, float* __restrict__ attn)
{
    __shared__ float As2[32][132];
    __shared__ float Bs2[32][68];
    const int bh = blockIdx.y;
    const int b = bh >> 4, h = bh & 15;
    const int l0 = blockIdx.x * 128;
    const int tid = threadIdx.x;
    const int tr = (tid >> 3) * 4;
    const int tc = (tid & 7) * 8;

    const float* qfb = qf + ((size_t)bh * Lc + l0) * Mc;
    const float* kvb = kv + (size_t)bh * Mc * DHc;

    float acc[4][8];
#pragma unroll
    for (int i = 0; i < 4; i++)
#pragma unroll
        for (int j = 0; j < 8; j++) acc[i][j] = 0.f;

    for (int kk = 0; kk < 256; kk += 32) {
#pragma unroll
        for (int i = 0; i < 4; i++) {
            int s = tid + i * 256;
            int r = s >> 3;
            int c4 = (s & 7) << 2;
            float4 a = *(const float4*)&qfb[(size_t)r * Mc + kk + c4];
            As2[c4 + 0][r] = a.x; As2[c4 + 1][r] = a.y;
            As2[c4 + 2][r] = a.z; As2[c4 + 3][r] = a.w;
        }
#pragma unroll
        for (int i = 0; i < 2; i++) {
            int s = tid + i * 256;
            int r = s >> 4;
            int c4 = (s & 15) << 2;
            *(float4*)&Bs2[r][c4] = *(const float4*)&kvb[(size_t)(kk + r) * 64 + c4];
        }
        __syncthreads();
#pragma unroll
        for (int k = 0; k < 32; k++) {
            float4 a0 = *(const float4*)&As2[k][tr];
            float4 b0 = *(const float4*)&Bs2[k][tc];
            float4 b1 = *(const float4*)&Bs2[k][tc + 4];
            float ra[4] = {a0.x, a0.y, a0.z, a0.w};
            float rb[8] = {b0.x, b0.y, b0.z, b0.w, b1.x, b1.y, b1.z, b1.w};
#pragma unroll
            for (int i = 0; i < 4; i++)
#pragma unroll
                for (int j = 0; j < 8; j++)
                    acc[i][j] += ra[i] * rb[j];
        }
        __syncthreads();
    }
#pragma unroll
    for (int i = 0; i < 4; i++) {
        float zz = z[(size_t)bh * Lc + l0 + tr + i];
        float* ap = &attn[(size_t)(b * Lc + l0 + tr + i) * Dc + h * DHc + tc];
        *(float4*)&ap[0] = make_float4(acc[i][0]*zz, acc[i][1]*zz, acc[i][2]*zz, acc[i][3]*zz);
        *(float4*)&ap[4] = make_float4(acc[i][4]*zz, acc[i][5]*zz, acc[i][6]*zz, acc[i][7]*zz);
    }
}

__global__ __launch_bounds__(256) void ln_dup_kernel(
    const float* __restrict__ y, const float* __restrict__ g,
    const float* __restrict__ beta, float* __restrict__ out)
{
    __shared__ float red[18];
    const int row = blockIdx.x;
    const int b = row >> 12, l = row & 4095;
    const int tid = threadIdx.x;
    const float* yr = y + (size_t)row * Dc;

    float v[4];
    float s = 0.f, ss = 0.f;
#pragma unroll
    for (int i = 0; i < 4; i++) {
        float t = yr[tid + i * 256];
        v[i] = t; s += t; ss += t * t;
    }
#pragma unroll
    for (int off = 16; off; off >>= 1) {
        s  += __shfl_xor_sync(0xffffffffu, s, off);
        ss += __shfl_xor_sync(0xffffffffu, ss, off);
    }
    const int w = tid >> 5, lane = tid & 31;
    if (lane == 0) { red[w] = s; red[8 + w] = ss; }
    __syncthreads();
    if (tid == 0) {
        float ts = 0.f, tss = 0.f;
#pragma unroll
        for (int i = 0; i < 8; i++) { ts += red[i]; tss += red[8 + i]; }
        float mean = ts * (1.0f / 1024.0f);
        float var = tss * (1.0f / 1024.0f) - mean * mean;
        red[16] = mean;
        red[17] = rsqrtf(var + 1e-5f);
    }
    __syncthreads();
    const float mean = red[16], rstd = red[17];
    float* o0 = out + ((size_t)b * 8192 + 2 * (size_t)l) * Dc;
#pragma unroll
    for (int i = 0; i < 4; i++) {
        int c = tid + i * 256;
        float o = (v[i] - mean) * rstd * g[c] + beta[c];
        o0[c] = o;
        o0[Dc + c] = o;
    }
}

// ============================================================
// host launch
// ============================================================
extern "C" void kernel_launch(void* const* d_in, const int* in_sizes, int n_in,
                              void* d_out, int out_size)
{
    const float* x    = (const float*)d_in[0];
    const float* Wq   = (const float*)d_in[1];
    const float* Wk   = (const float*)d_in[2];
    const float* Wv   = (const float*)d_in[3];
    const float* Wo   = (const float*)d_in[4];
    const float* proj = (const float*)d_in[5];
    const float* ln_g = (const float*)d_in[6];
    const float* ln_b = (const float*)d_in[7];
    float* out = (float*)d_out;

    float *q, *k, *v, *qf, *kf, *kv, *ksum, *z, *attn, *y;
    __nv_bfloat16 *ahi, *alo, *bthi, *btlo;
    cudaGetSymbolAddress((void**)&q,    g_q);
    cudaGetSymbolAddress((void**)&k,    g_k);
    cudaGetSymbolAddress((void**)&v,    g_v);
    cudaGetSymbolAddress((void**)&qf,   g_qf);
    cudaGetSymbolAddress((void**)&kf,   g_kf);
    cudaGetSymbolAddress((void**)&kv,   g_kv);
    cudaGetSymbolAddress((void**)&ksum, g_ksum);
    cudaGetSymbolAddress((void**)&z,    g_z);
    cudaGetSymbolAddress((void**)&attn, g_attn);
    cudaGetSymbolAddress((void**)&y,    g_y);
    cudaGetSymbolAddress((void**)&ahi,  g_ahi);
    cudaGetSymbolAddress((void**)&alo,  g_alo);
    cudaGetSymbolAddress((void**)&bthi, g_bthi);
    cudaGetSymbolAddress((void**)&btlo, g_btlo);

    const float qscale = 0.35355339059327379f;  // 64^-0.25

    const int feat_smem = FEAT_SMEM_FLOATS * (int)sizeof(float);
    cudaFuncSetAttribute(feature_kernel,
                         cudaFuncAttributeMaxDynamicSharedMemorySize, feat_smem);

    const int n4 = ROWS * Dc / 4;
    dim3 tgrid(32, 32), tblk(32, 8);
    dim3 ggrid(8, 64);   // N tiles x M tiles

    // split activations once (used by Q, K, V GEMMs)
    split_kernel<<<n4 / 256, 256>>>(x, ahi, alo, n4);

    tsplit_kernel<<<tgrid, tblk>>>(Wq, bthi, btlo);
    mma_gemm_kernel<<<ggrid, 256>>>(ahi, alo, bthi, btlo, q, qscale, 0);
    tsplit_kernel<<<tgrid, tblk>>>(Wk, bthi, btlo);
    mma_gemm_kernel<<<ggrid, 256>>>(ahi, alo, bthi, btlo, k, qscale, 0);
    tsplit_kernel<<<tgrid, tblk>>>(Wv, bthi, btlo);
    mma_gemm_kernel<<<ggrid, 256>>>(ahi, alo, bthi, btlo, v, 1.0f, 0);

    feature_kernel<<<dim3(Lc / 32, BHc), 256, feat_smem>>>(q, proj, qf);
    feature_kernel<<<dim3(Lc / 32, BHc), 256, feat_smem>>>(k, proj, kf);

    cudaMemsetAsync(kv,   0, (size_t)BHc * Mc * DHc * sizeof(float), 0);
    cudaMemsetAsync(ksum, 0, (size_t)BHc * Mc * sizeof(float), 0);
    kv_kernel<<<dim3(BHc, 16), 256>>>(kf, v, kv, ksum);

    z_kernel<<<dim3(Lc / 8, BHc), 256>>>(qf, ksum, z);
    attn_kernel<<<dim3(Lc / 128, BHc), 256>>>(qf, kv, z, attn);

    // O projection + exact GELU
    split_kernel<<<n4 / 256, 256>>>(attn, ahi, alo, n4);
    tsplit_kernel<<<tgrid, tblk>>>(Wo, bthi, btlo);
    mma_gemm_kernel<<<ggrid, 256>>>(ahi, alo, bthi, btlo, y, 1.0f, 1);

    ln_dup_kernel<<<ROWS, 256>>>(y, ln_g, ln_b, out);
}